// round 3
// baseline (speedup 1.0000x reference)
#include <cuda_runtime.h>

#define BATCH 32
#define CIN   64
#define COUT  64
#define HW    64
#define PLANE (HW * HW)        // 4096
#define KK    9
#define WSTRIDE 68             // padded o-stride (floats) to cut STS bank conflicts
#define WSMEM  (CIN * KK * WSTRIDE)   // 39168 floats = 156672 bytes

#define FMA2(a, s, w) asm("fma.rn.f32x2 %0, %1, %2, %0;" : "+l"(a) : "l"(s), "l"(w))

// Scratch: deform-conv output + per-(b,o) reduction stats.
__device__ float g_d[BATCH * COUT * PLANE];   // ~33.5 MB
__device__ float g_sum[BATCH * COUT];
__device__ float g_sqs[BATCH * COUT];

__global__ void zero_stats_kernel() {
    int i = blockIdx.x * blockDim.x + threadIdx.x;
    if (i < BATCH * COUT) { g_sum[i] = 0.f; g_sqs[i] = 0.f; }
}

// Block: 512 pixels (8 rows) x all 64 outputs. 256 threads.
// Thread: 4 pixels (q, q+128, q+256, q+384) x 32 outputs (half o, by t>>7).
__global__ __launch_bounds__(256, 1)
void deform_kernel(const float* __restrict__ x,
                   const float* __restrict__ offset,
                   const float* __restrict__ weight)
{
    extern __shared__ float w_sh[];  // [c][k][o] : (c*9+k)*WSTRIDE + o

    // Stage weights [o][c][k] -> smem [(c*9+k)*68 + o]. Coalesced LDG.
    for (int idx = threadIdx.x; idx < COUT * CIN * KK; idx += 256) {
        int o  = idx / (CIN * KK);
        int ck = idx % (CIN * KK);
        w_sh[ck * WSTRIDE + o] = weight[idx];
    }
    __syncthreads();

    const int t   = threadIdx.x;
    const int q   = t & 127;          // pixel lane within the 512-pixel tile
    const int oh  = t >> 7;           // output half: 0 -> o[0..31], 1 -> o[32..63]
    const int b   = blockIdx.x >> 3;
    const int seg = blockIdx.x & 7;   // which 8-row band

    int pix[4], prow[4], pcol[4];
    #pragma unroll
    for (int j = 0; j < 4; j++) {
        pix[j]  = seg * 512 + 128 * j + q;
        prow[j] = pix[j] >> 6;
        pcol[j] = pix[j] & 63;
    }

    const float* xb   = x + (size_t)b * CIN * PLANE;
    const float* offb = offset + (size_t)b * (2 * KK) * PLANE;

    // 4 pixels x 16 packed-pairs (32 outs) = 128 fp32 accumulators
    unsigned long long acc[4][16];
    #pragma unroll
    for (int j = 0; j < 4; j++)
        #pragma unroll
        for (int i = 0; i < 16; i++) acc[j][i] = 0ull;

    #pragma unroll 1
    for (int k = 0; k < KK; k++) {
        const int ky = k / 3;
        const int kx = k - 3 * ky;

        int i00[4], i01[4], i10[4], i11[4];
        float W00[4], W01[4], W10[4], W11[4];
        #pragma unroll
        for (int j = 0; j < 4; j++) {
            const float oy = __ldg(offb + (2 * k)     * PLANE + pix[j]);
            const float ox = __ldg(offb + (2 * k + 1) * PLANE + pix[j]);
            const float py = (float)(prow[j] - 1 + ky) + oy;
            const float px = (float)(pcol[j] - 1 + kx) + ox;
            const float y0f = floorf(py), x0f = floorf(px);
            const float fy = py - y0f,  fx = px - x0f;
            const int y0 = (int)y0f, x0 = (int)x0f;
            const int y1 = y0 + 1,   x1 = x0 + 1;
            const float vy0 = (y0 >= 0 && y0 < HW) ? 1.f : 0.f;
            const float vy1 = (y1 >= 0 && y1 < HW) ? 1.f : 0.f;
            const float vx0 = (x0 >= 0 && x0 < HW) ? 1.f : 0.f;
            const float vx1 = (x1 >= 0 && x1 < HW) ? 1.f : 0.f;
            const int cy0 = min(max(y0, 0), HW - 1), cy1 = min(max(y1, 0), HW - 1);
            const int cx0 = min(max(x0, 0), HW - 1), cx1 = min(max(x1, 0), HW - 1);
            W00[j] = (1.f - fy) * (1.f - fx) * vy0 * vx0;
            W01[j] = (1.f - fy) * fx        * vy0 * vx1;
            W10[j] = fy        * (1.f - fx) * vy1 * vx0;
            W11[j] = fy        * fx         * vy1 * vx1;
            i00[j] = cy0 * HW + cx0; i01[j] = cy0 * HW + cx1;
            i10[j] = cy1 * HW + cx0; i11[j] = cy1 * HW + cx1;
        }

        const float* w_base = w_sh + k * WSTRIDE + oh * 32;

        #pragma unroll 1
        for (int c = 0; c < CIN; c++) {
            const float* p = xb + c * PLANE;
            unsigned long long s2[4];
            #pragma unroll
            for (int j = 0; j < 4; j++) {
                float s = W00[j] * __ldg(p + i00[j]) + W01[j] * __ldg(p + i01[j])
                        + W10[j] * __ldg(p + i10[j]) + W11[j] * __ldg(p + i11[j]);
                asm("mov.b64 %0, {%1, %1};" : "=l"(s2[j]) : "f"(s));
            }
            const ulonglong2* wc =
                reinterpret_cast<const ulonglong2*>(w_base + (size_t)c * (KK * WSTRIDE));
            #pragma unroll
            for (int h = 0; h < 2; h++) {
                const ulonglong2 w0 = wc[4 * h + 0];
                const ulonglong2 w1 = wc[4 * h + 1];
                const ulonglong2 w2 = wc[4 * h + 2];
                const ulonglong2 w3 = wc[4 * h + 3];
                #pragma unroll
                for (int j = 0; j < 4; j++) {
                    FMA2(acc[j][8 * h + 0], s2[j], w0.x);
                    FMA2(acc[j][8 * h + 1], s2[j], w0.y);
                    FMA2(acc[j][8 * h + 2], s2[j], w1.x);
                    FMA2(acc[j][8 * h + 3], s2[j], w1.y);
                    FMA2(acc[j][8 * h + 4], s2[j], w2.x);
                    FMA2(acc[j][8 * h + 5], s2[j], w2.y);
                    FMA2(acc[j][8 * h + 6], s2[j], w3.x);
                    FMA2(acc[j][8 * h + 7], s2[j], w3.y);
                }
            }
        }
    }

    // Epilogue: write d, reduce per-(b,o) stats across the warp (lanes = pixels).
    const int lane = t & 31;
    const size_t dbase = (size_t)b * COUT * PLANE;
    #pragma unroll
    for (int oo = 0; oo < 16; oo++) {
        const int o0 = oh * 32 + 2 * oo;
        float s0 = 0.f, q0 = 0.f, s1 = 0.f, q1 = 0.f;
        #pragma unroll
        for (int j = 0; j < 4; j++) {
            const float a0 = __uint_as_float((unsigned)(acc[j][oo] & 0xffffffffull));
            const float a1 = __uint_as_float((unsigned)(acc[j][oo] >> 32));
            g_d[dbase + (size_t)o0 * PLANE + pix[j]]       = a0;
            g_d[dbase + (size_t)(o0 + 1) * PLANE + pix[j]] = a1;
            s0 += a0; q0 += a0 * a0; s1 += a1; q1 += a1 * a1;
        }
        #pragma unroll
        for (int d = 16; d > 0; d >>= 1) {
            s0 += __shfl_xor_sync(0xffffffffu, s0, d);
            q0 += __shfl_xor_sync(0xffffffffu, q0, d);
            s1 += __shfl_xor_sync(0xffffffffu, s1, d);
            q1 += __shfl_xor_sync(0xffffffffu, q1, d);
        }
        if (lane == 0) {
            atomicAdd(&g_sum[b * COUT + o0],     s0);
            atomicAdd(&g_sqs[b * COUT + o0],     q0);
            atomicAdd(&g_sum[b * COUT + o0 + 1], s1);
            atomicAdd(&g_sqs[b * COUT + o0 + 1], q1);
        }
    }
}

__global__ void norm_kernel(const float* __restrict__ gamma_p,
                            const float* __restrict__ beta_p,
                            float* __restrict__ out)
{
    const int bo = blockIdx.x;  // b*COUT + o
    const float sum = g_sum[bo];
    const float sqs = g_sqs[bo];
    const float n = (float)PLANE;
    const float mu = sum / n;
    float var = (sqs - sum * sum / n) / (n - 1.f);
    var = fmaxf(var, 0.f);
    const float sd = sqrtf(var);
    const float gamma = __ldg(gamma_p);
    const float beta  = __ldg(beta_p);
    const float scale = gamma / (sd + 1e-8f);

    const float4* dsrc = reinterpret_cast<const float4*>(g_d + (size_t)bo * PLANE);
    float4* o = reinterpret_cast<float4*>(out + (size_t)bo * PLANE);
    for (int i = threadIdx.x; i < PLANE / 4; i += blockDim.x) {
        float4 v = dsrc[i];
        float4 r;
        r.x = tanhf((v.x - mu) * scale + beta);
        r.y = tanhf((v.y - mu) * scale + beta);
        r.z = tanhf((v.z - mu) * scale + beta);
        r.w = tanhf((v.w - mu) * scale + beta);
        o[i] = r;
    }
}

extern "C" void kernel_launch(void* const* d_in, const int* in_sizes, int n_in,
                              void* d_out, int out_size)
{
    const float* x      = (const float*)d_in[0];
    const float* offset = (const float*)d_in[1];
    const float* weight = (const float*)d_in[2];
    const float* gamma  = (const float*)d_in[3];
    const float* beta   = (const float*)d_in[4];

    cudaFuncSetAttribute(deform_kernel,
                         cudaFuncAttributeMaxDynamicSharedMemorySize,
                         WSMEM * (int)sizeof(float));

    zero_stats_kernel<<<4, 512>>>();
    deform_kernel<<<(BATCH * PLANE) / 512, 256, WSMEM * sizeof(float)>>>(x, offset, weight);
    norm_kernel<<<BATCH * COUT, 256>>>(gamma, beta, (float*)d_out);
}

// round 4
// speedup vs baseline: 1.3043x; 1.3043x over previous
#include <cuda_runtime.h>

#define BATCH 32
#define CIN   64
#define COUT  64
#define HW    64
#define PLANE (HW * HW)          // 4096
#define KK    9
#define OH    32                 // outputs per block (one half of COUT)
#define WHALF (CIN * KK * OH)    // 18432 floats = 73728 bytes

#define FMA2(a, s, w) asm("fma.rn.f32x2 %0, %1, %2, %0;" : "+l"(a) : "l"(s), "l"(w))

// Scratch: deform-conv output (pre-norm)
__device__ float g_d[BATCH * COUT * PLANE];   // ~33.5 MB

// Block: 256 pixels (4 rows) x 32 outputs (one o-half). 256 threads, 1 pixel each.
__global__ __launch_bounds__(256, 3)
void deform_kernel(const float* __restrict__ x,
                   const float* __restrict__ offset,
                   const float* __restrict__ weight)
{
    extern __shared__ float w_sh[];   // [(c*9+k)*32 + o], o in [0,32)

    const int t    = threadIdx.x;
    const int half = blockIdx.x & 1;
    const int seg  = (blockIdx.x >> 1) & 15;
    const int b    = blockIdx.x >> 5;

    // ---- Stage weight half [o][c][k] -> smem [(c*9+k)*32 + o] ----
    // lane = o (conflict-free STS), strided LDG.128 over ck (one-time cost).
    {
        const int o    = t & 31;                 // = lane
        const int part = t >> 5;                 // 8 parts x 18 float4 = 576 ck
        const float4* wrow =
            reinterpret_cast<const float4*>(weight + (size_t)(half * 32 + o) * (CIN * KK));
        #pragma unroll
        for (int jj = 0; jj < 18; jj++) {
            const int j = part * 18 + jj;        // float4 index; ck = 4*j
            const float4 v = __ldg(wrow + j);
            w_sh[(4 * j + 0) * 32 + o] = v.x;
            w_sh[(4 * j + 1) * 32 + o] = v.y;
            w_sh[(4 * j + 2) * 32 + o] = v.z;
            w_sh[(4 * j + 3) * 32 + o] = v.w;
        }
    }
    __syncthreads();

    const int pix = seg * 256 + t;
    const int row = pix >> 6;
    const int col = pix & 63;

    const float* xb   = x + (size_t)b * CIN * PLANE;
    const float* offb = offset + (size_t)b * (2 * KK) * PLANE;

    // 32 fp32 accumulators packed as 16 f32x2 (o-pairs)
    unsigned long long acc[16];
    #pragma unroll
    for (int i = 0; i < 16; i++) acc[i] = 0ull;

    #pragma unroll 1
    for (int k = 0; k < KK; k++) {
        const int ky = k / 3;
        const int kx = k - 3 * ky;
        const float oy = __ldg(offb + (2 * k)     * PLANE + pix);
        const float ox = __ldg(offb + (2 * k + 1) * PLANE + pix);
        const float py = (float)(row - 1 + ky) + oy;
        const float px = (float)(col - 1 + kx) + ox;
        const float y0f = floorf(py), x0f = floorf(px);
        const float fy = py - y0f,  fx = px - x0f;
        const int y0 = (int)y0f, x0 = (int)x0f;
        const int y1 = y0 + 1,   x1 = x0 + 1;
        const float vy0 = (y0 >= 0 && y0 < HW) ? 1.f : 0.f;
        const float vy1 = (y1 >= 0 && y1 < HW) ? 1.f : 0.f;
        const float vx0 = (x0 >= 0 && x0 < HW) ? 1.f : 0.f;
        const float vx1 = (x1 >= 0 && x1 < HW) ? 1.f : 0.f;
        const int cy0 = min(max(y0, 0), HW - 1), cy1 = min(max(y1, 0), HW - 1);
        const int cx0 = min(max(x0, 0), HW - 1), cx1 = min(max(x1, 0), HW - 1);
        const float W00 = (1.f - fy) * (1.f - fx) * vy0 * vx0;
        const float W01 = (1.f - fy) * fx        * vy0 * vx1;
        const float W10 = fy        * (1.f - fx) * vy1 * vx0;
        const float W11 = fy        * fx         * vy1 * vx1;
        const int i00 = cy0 * HW + cx0, i01 = cy0 * HW + cx1;
        const int i10 = cy1 * HW + cx0, i11 = cy1 * HW + cx1;

        // Prefetch c = 0 samples
        const float* p = xb;
        float a00 = __ldg(p + i00), a01 = __ldg(p + i01);
        float a10 = __ldg(p + i10), a11 = __ldg(p + i11);

        #pragma unroll 2
        for (int c = 0; c < CIN; c++) {
            // Prefetch next channel's samples (clamped pointer at the end; values unused)
            const float* pn = (c < CIN - 1) ? (p + PLANE) : p;
            const float b00 = __ldg(pn + i00), b01 = __ldg(pn + i01);
            const float b10 = __ldg(pn + i10), b11 = __ldg(pn + i11);

            const float s = W00 * a00 + W01 * a01 + W10 * a10 + W11 * a11;
            unsigned long long s2;
            asm("mov.b64 %0, {%1, %1};" : "=l"(s2) : "f"(s));

            const ulonglong2* wc =
                reinterpret_cast<const ulonglong2*>(w_sh + (size_t)(c * KK + k) * 32);
            #pragma unroll
            for (int g = 0; g < 8; g++) {
                const ulonglong2 wv = wc[g];     // broadcast LDS.128
                FMA2(acc[2 * g],     s2, wv.x);
                FMA2(acc[2 * g + 1], s2, wv.y);
            }

            a00 = b00; a01 = b01; a10 = b10; a11 = b11;
            p = pn;
        }
    }

    // Epilogue: write d (coalesced per-o planes)
    float* dst = g_d + ((size_t)b * COUT + half * 32) * PLANE + pix;
    #pragma unroll
    for (int i = 0; i < 16; i++) {
        const float a0 = __uint_as_float((unsigned)(acc[i] & 0xffffffffull));
        const float a1 = __uint_as_float((unsigned)(acc[i] >> 32));
        dst[(size_t)(2 * i)     * PLANE] = a0;
        dst[(size_t)(2 * i + 1) * PLANE] = a1;
    }
}

// One block per (b, o) plane: single-read stats + normalize + tanh.
__global__ __launch_bounds__(256)
void norm_kernel(const float* __restrict__ gamma_p,
                 const float* __restrict__ beta_p,
                 float* __restrict__ out)
{
    __shared__ float red[16];
    __shared__ float bcast[2];

    const int bo = blockIdx.x;
    const int t  = threadIdx.x;
    const float4* src = reinterpret_cast<const float4*>(g_d + (size_t)bo * PLANE);

    float4 v[4];
    float s = 0.f, q = 0.f;
    #pragma unroll
    for (int i = 0; i < 4; i++) {
        v[i] = src[t + 256 * i];
        s += v[i].x + v[i].y + v[i].z + v[i].w;
        q += v[i].x * v[i].x + v[i].y * v[i].y + v[i].z * v[i].z + v[i].w * v[i].w;
    }
    #pragma unroll
    for (int d = 16; d > 0; d >>= 1) {
        s += __shfl_xor_sync(0xffffffffu, s, d);
        q += __shfl_xor_sync(0xffffffffu, q, d);
    }
    const int w = t >> 5, lane = t & 31;
    if (lane == 0) { red[w] = s; red[8 + w] = q; }
    __syncthreads();
    if (t == 0) {
        float S = 0.f, Q = 0.f;
        #pragma unroll
        for (int i = 0; i < 8; i++) { S += red[i]; Q += red[8 + i]; }
        const float n  = (float)PLANE;
        const float mu = S / n;
        float var = (Q - S * S / n) / (n - 1.f);
        var = fmaxf(var, 0.f);
        const float sd = sqrtf(var);
        bcast[0] = mu;
        bcast[1] = __ldg(gamma_p) / (sd + 1e-8f);
    }
    __syncthreads();
    const float mu    = bcast[0];
    const float scale = bcast[1];
    const float beta  = __ldg(beta_p);

    float4* o = reinterpret_cast<float4*>(out + (size_t)bo * PLANE);
    #pragma unroll
    for (int i = 0; i < 4; i++) {
        float4 r;
        r.x = tanhf((v[i].x - mu) * scale + beta);
        r.y = tanhf((v[i].y - mu) * scale + beta);
        r.z = tanhf((v[i].z - mu) * scale + beta);
        r.w = tanhf((v[i].w - mu) * scale + beta);
        o[t + 256 * i] = r;
    }
}

extern "C" void kernel_launch(void* const* d_in, const int* in_sizes, int n_in,
                              void* d_out, int out_size)
{
    const float* x      = (const float*)d_in[0];
    const float* offset = (const float*)d_in[1];
    const float* weight = (const float*)d_in[2];
    const float* gamma  = (const float*)d_in[3];
    const float* beta   = (const float*)d_in[4];

    cudaFuncSetAttribute(deform_kernel,
                         cudaFuncAttributeMaxDynamicSharedMemorySize,
                         WHALF * (int)sizeof(float));

    // grid: b (32) x seg (16) x half (2) = 1024 blocks
    deform_kernel<<<BATCH * 16 * 2, 256, WHALF * sizeof(float)>>>(x, offset, weight);
    norm_kernel<<<BATCH * COUT, 256>>>(gamma, beta, (float*)d_out);
}

// round 12
// speedup vs baseline: 1.3621x; 1.0443x over previous
#include <cuda_runtime.h>

#define BATCH 32
#define CIN   64
#define COUT  64
#define HW    64
#define PLANE 4096
#define KK    9
#define SSTR  144   // padded words per channel row of S (max used index 139)

#define FMA2(a, s, w) asm("fma.rn.f32x2 %0, %1, %2, %0;" : "+l"(a) : "l"(s), "l"(w))

// Scratch
__device__ float g_d[BATCH * COUT * PLANE];   // pre-norm conv output (~33.5 MB)
__device__ float g_wt[KK * CIN * COUT];       // transposed weights [k][c][o]

__global__ void transpose_w(const float* __restrict__ w) {
    int idx = blockIdx.x * 256 + threadIdx.x;
    if (idx < COUT * CIN * KK) {
        int o = idx / (CIN * KK);
        int r = idx % (CIN * KK);
        int c = r / KK;
        int k = r % KK;
        g_wt[(k * CIN + c) * COUT + o] = w[idx];
    }
}

__global__ void dummy_kernel() {}

// Block: 128 pixels x 64 outputs. 256 threads.
// Per k: Phase A gathers S[c][pix] to smem (no duplication), Phase B = register-tiled GEMM.
__global__ __launch_bounds__(256, 3)
void deform_kernel(const float* __restrict__ x,
                   const float* __restrict__ offset)
{
    __shared__ float S[CIN * SSTR];   // 36864 B

    const int t   = threadIdx.x;
    const int seg = blockIdx.x & 31;
    const int b   = blockIdx.x >> 5;

    // Phase A role: 2 threads per pixel, 32 channels each
    const int pixA  = t & 127;
    const int chalf = t >> 7;
    const int gpixA = seg * 128 + pixA;
    const int rowA  = gpixA >> 6;
    const int colA  = gpixA & 63;
    // Swizzled element address for this pixel (conflict-free writes, low-conflict reads)
    float* sdstA = S + (chalf * 32) * SSTR + pixA + ((pixA >> 5) << 2);

    // Phase B role: og = 4-output group, pg = 8-pixel group
    const int og = t >> 4;
    const int pg = t & 15;
    const float* sbase = S + pg * 8 + ((pg >> 2) << 2);

    const float* xb   = x + (size_t)b * CIN * PLANE;
    const float* offb = offset + (size_t)b * (2 * KK) * PLANE;

    // acc[pixel-pair][o] : 8 pixels x 4 outs = 16 packed f32x2
    unsigned long long acc[4][4];
    #pragma unroll
    for (int i = 0; i < 4; i++)
        #pragma unroll
        for (int j = 0; j < 4; j++) acc[i][j] = 0ull;

    #pragma unroll 1
    for (int k = 0; k < KK; k++) {
        if (k > 0) __syncthreads();   // previous Phase B done reading S

        // ---------------- Phase A: sample into S ----------------
        {
            const int ky = k / 3;
            const int kx = k - 3 * ky;
            const float oy = __ldg(offb + (2 * k)     * PLANE + gpixA);
            const float ox = __ldg(offb + (2 * k + 1) * PLANE + gpixA);
            const float py = (float)(rowA - 1 + ky) + oy;
            const float px = (float)(colA - 1 + kx) + ox;
            const float y0f = floorf(py), x0f = floorf(px);
            const float fy = py - y0f,  fx = px - x0f;
            const int y0 = (int)y0f, x0 = (int)x0f;
            const int y1 = y0 + 1,   x1 = x0 + 1;
            const float vy0 = (y0 >= 0 && y0 < HW) ? 1.f : 0.f;
            const float vy1 = (y1 >= 0 && y1 < HW) ? 1.f : 0.f;
            const float vx0 = (x0 >= 0 && x0 < HW) ? 1.f : 0.f;
            const float vx1 = (x1 >= 0 && x1 < HW) ? 1.f : 0.f;
            const int cy0 = min(max(y0, 0), HW - 1), cy1 = min(max(y1, 0), HW - 1);
            const int cx0 = min(max(x0, 0), HW - 1), cx1 = min(max(x1, 0), HW - 1);
            const float W00 = (1.f - fy) * (1.f - fx) * vy0 * vx0;
            const float W01 = (1.f - fy) * fx        * vy0 * vx1;
            const float W10 = fy        * (1.f - fx) * vy1 * vx0;
            const float W11 = fy        * fx         * vy1 * vx1;

            const float* p00 = xb + (size_t)(chalf * 32) * PLANE + cy0 * HW + cx0;
            const float* p01 = xb + (size_t)(chalf * 32) * PLANE + cy0 * HW + cx1;
            const float* p10 = xb + (size_t)(chalf * 32) * PLANE + cy1 * HW + cx0;
            const float* p11 = xb + (size_t)(chalf * 32) * PLANE + cy1 * HW + cx1;

            #pragma unroll 8
            for (int cc = 0; cc < 32; cc++) {
                const float a00 = __ldg(p00 + cc * PLANE);
                const float a01 = __ldg(p01 + cc * PLANE);
                const float a10 = __ldg(p10 + cc * PLANE);
                const float a11 = __ldg(p11 + cc * PLANE);
                float s = W00 * a00;
                s = fmaf(W01, a01, s);
                s = fmaf(W10, a10, s);
                s = fmaf(W11, a11, s);
                sdstA[cc * SSTR] = s;
            }
        }
        __syncthreads();

        // ---------------- Phase B: GEMM from S x Wt ----------------
        {
            const float* wrow = g_wt + (size_t)k * CIN * COUT + og * 4;
            float4 wv = __ldg((const float4*)wrow);

            #pragma unroll 2
            for (int c = 0; c < CIN; c++) {
                const int cn = (c < CIN - 1) ? (c + 1) : c;
                const float4 wn = __ldg((const float4*)(wrow + cn * COUT));

                const ulonglong2 sA = *(const ulonglong2*)(sbase + c * SSTR);
                const ulonglong2 sB = *(const ulonglong2*)(sbase + c * SSTR + 4);

                unsigned long long w2[4];
                asm("mov.b64 %0, {%1, %1};" : "=l"(w2[0]) : "f"(wv.x));
                asm("mov.b64 %0, {%1, %1};" : "=l"(w2[1]) : "f"(wv.y));
                asm("mov.b64 %0, {%1, %1};" : "=l"(w2[2]) : "f"(wv.z));
                asm("mov.b64 %0, {%1, %1};" : "=l"(w2[3]) : "f"(wv.w));

                #pragma unroll
                for (int oo = 0; oo < 4; oo++) {
                    FMA2(acc[0][oo], sA.x, w2[oo]);
                    FMA2(acc[1][oo], sA.y, w2[oo]);
                    FMA2(acc[2][oo], sB.x, w2[oo]);
                    FMA2(acc[3][oo], sB.y, w2[oo]);
                }
                wv = wn;
            }
        }
    }

    // Epilogue: write d. Lanes of a warp cover all 128 pixels for each o -> coalesced.
    float* dbase = g_d + ((size_t)b * COUT + og * 4) * PLANE + seg * 128 + pg * 8;
    #pragma unroll
    for (int oo = 0; oo < 4; oo++) {
        float4 v0, v1;
        v0.x = __uint_as_float((unsigned)(acc[0][oo] & 0xffffffffull));
        v0.y = __uint_as_float((unsigned)(acc[0][oo] >> 32));
        v0.z = __uint_as_float((unsigned)(acc[1][oo] & 0xffffffffull));
        v0.w = __uint_as_float((unsigned)(acc[1][oo] >> 32));
        v1.x = __uint_as_float((unsigned)(acc[2][oo] & 0xffffffffull));
        v1.y = __uint_as_float((unsigned)(acc[2][oo] >> 32));
        v1.z = __uint_as_float((unsigned)(acc[3][oo] & 0xffffffffull));
        v1.w = __uint_as_float((unsigned)(acc[3][oo] >> 32));
        *(float4*)(dbase + (size_t)oo * PLANE)     = v0;
        *(float4*)(dbase + (size_t)oo * PLANE + 4) = v1;
    }
}

// One block per (b, o) plane: single-read stats + normalize + tanh.
__global__ __launch_bounds__(256)
void norm_kernel(const float* __restrict__ gamma_p,
                 const float* __restrict__ beta_p,
                 float* __restrict__ out)
{
    __shared__ float red[16];
    __shared__ float bcast[2];

    const int bo = blockIdx.x;
    const int t  = threadIdx.x;
    const float4* src = reinterpret_cast<const float4*>(g_d + (size_t)bo * PLANE);

    float4 v[4];
    float s = 0.f, q = 0.f;
    #pragma unroll
    for (int i = 0; i < 4; i++) {
        v[i] = src[t + 256 * i];
        s += v[i].x + v[i].y + v[i].z + v[i].w;
        q += v[i].x * v[i].x + v[i].y * v[i].y + v[i].z * v[i].z + v[i].w * v[i].w;
    }
    #pragma unroll
    for (int d = 16; d > 0; d >>= 1) {
        s += __shfl_xor_sync(0xffffffffu, s, d);
        q += __shfl_xor_sync(0xffffffffu, q, d);
    }
    const int w = t >> 5, lane = t & 31;
    if (lane == 0) { red[w] = s; red[8 + w] = q; }
    __syncthreads();
    if (t == 0) {
        float S = 0.f, Q = 0.f;
        #pragma unroll
        for (int i = 0; i < 8; i++) { S += red[i]; Q += red[8 + i]; }
        const float n  = (float)PLANE;
        const float mu = S / n;
        float var = (Q - S * S / n) / (n - 1.f);
        var = fmaxf(var, 0.f);
        const float sd = sqrtf(var);
        bcast[0] = mu;
        bcast[1] = __ldg(gamma_p) / (sd + 1e-8f);
    }
    __syncthreads();
    const float mu    = bcast[0];
    const float scale = bcast[1];
    const float beta  = __ldg(beta_p);

    float4* o = reinterpret_cast<float4*>(out + (size_t)bo * PLANE);
    #pragma unroll
    for (int i = 0; i < 4; i++) {
        float4 r;
        r.x = tanhf((v[i].x - mu) * scale + beta);
        r.y = tanhf((v[i].y - mu) * scale + beta);
        r.z = tanhf((v[i].z - mu) * scale + beta);
        r.w = tanhf((v[i].w - mu) * scale + beta);
        o[t + 256 * i] = r;
    }
}

extern "C" void kernel_launch(void* const* d_in, const int* in_sizes, int n_in,
                              void* d_out, int out_size)
{
    const float* x      = (const float*)d_in[0];
    const float* offset = (const float*)d_in[1];
    const float* weight = (const float*)d_in[2];
    const float* gamma  = (const float*)d_in[3];
    const float* beta   = (const float*)d_in[4];

    transpose_w<<<144, 256>>>(weight);
    deform_kernel<<<BATCH * 32, 256>>>(x, offset);         // 1024 blocks
    norm_kernel<<<BATCH * COUT, 256>>>(gamma, beta, (float*)d_out);
    dummy_kernel<<<1, 32>>>();   // pad launch count so ncu (-s 5) lands on deform_kernel
}

// round 14
// speedup vs baseline: 1.4689x; 1.0784x over previous
#include <cuda_runtime.h>

#define BATCH 32
#define CIN   64
#define COUT  64
#define HW    64
#define PLANE 4096
#define KK    9
#define SSTR  144   // padded words per channel row of S (max used index 139)

#define FMA2(a, s, w) asm("fma.rn.f32x2 %0, %1, %2, %0;" : "+l"(a) : "l"(s), "l"(w))

// Scratch
__device__ float g_d[BATCH * COUT * PLANE];            // pre-norm conv output (~33.5 MB)
__device__ unsigned long long g_wt2[KK * CIN * COUT];  // weights pre-duplicated (w,w) [k][c][o]

__global__ void transpose_w(const float* __restrict__ w) {
    int idx = blockIdx.x * 256 + threadIdx.x;
    if (idx < COUT * CIN * KK) {
        int o = idx / (CIN * KK);
        int r = idx % (CIN * KK);
        int c = r / KK;
        int k = r % KK;
        const float v = w[idx];
        unsigned long long d;
        asm("mov.b64 %0, {%1, %1};" : "=l"(d) : "f"(v));
        g_wt2[(k * CIN + c) * COUT + o] = d;
    }
}

__global__ void dummy_kernel() {}

// Block: 128 pixels x 64 outputs. 256 threads.
// Per k: Phase A gathers S[c][pix] to smem (no duplication), Phase B = register-tiled GEMM.
__global__ __launch_bounds__(256, 2)
void deform_kernel(const float* __restrict__ x,
                   const float* __restrict__ offset)
{
    __shared__ float S[CIN * SSTR];   // 36864 B

    const int t   = threadIdx.x;
    const int seg = blockIdx.x & 31;
    const int b   = blockIdx.x >> 5;

    // Phase A role: 2 threads per pixel, 32 channels each
    const int pixA  = t & 127;
    const int chalf = t >> 7;
    const int gpixA = seg * 128 + pixA;
    const int rowA  = gpixA >> 6;
    const int colA  = gpixA & 63;
    float* sdstA = S + (chalf * 32) * SSTR + pixA + ((pixA >> 5) << 2);

    // Phase B role: og = 4-output group, pg = 8-pixel group
    const int og = t >> 4;
    const int pg = t & 15;
    const float* sbase = S + pg * 8 + ((pg >> 2) << 2);

    const float* xb   = x + (size_t)b * CIN * PLANE;
    const float* offb = offset + (size_t)b * (2 * KK) * PLANE;

    // acc[pixel-pair][o] : 8 pixels x 4 outs = 16 packed f32x2
    unsigned long long acc[4][4];
    #pragma unroll
    for (int i = 0; i < 4; i++)
        #pragma unroll
        for (int j = 0; j < 4; j++) acc[i][j] = 0ull;

    #pragma unroll 1
    for (int k = 0; k < KK; k++) {
        if (k > 0) __syncthreads();   // previous Phase B done reading S

        // ---------------- Phase A: sample into S ----------------
        {
            const int ky = k / 3;
            const int kx = k - 3 * ky;
            const float oy = __ldg(offb + (2 * k)     * PLANE + gpixA);
            const float ox = __ldg(offb + (2 * k + 1) * PLANE + gpixA);
            const float py = (float)(rowA - 1 + ky) + oy;
            const float px = (float)(colA - 1 + kx) + ox;
            const float y0f = floorf(py), x0f = floorf(px);
            const float fy = py - y0f,  fx = px - x0f;
            const int y0 = (int)y0f, x0 = (int)x0f;
            const int y1 = y0 + 1,   x1 = x0 + 1;
            const float vy0 = (y0 >= 0 && y0 < HW) ? 1.f : 0.f;
            const float vy1 = (y1 >= 0 && y1 < HW) ? 1.f : 0.f;
            const float vx0 = (x0 >= 0 && x0 < HW) ? 1.f : 0.f;
            const float vx1 = (x1 >= 0 && x1 < HW) ? 1.f : 0.f;
            const int cy0 = min(max(y0, 0), HW - 1), cy1 = min(max(y1, 0), HW - 1);
            const int cx0 = min(max(x0, 0), HW - 1), cx1 = min(max(x1, 0), HW - 1);
            const float W00 = (1.f - fy) * (1.f - fx) * vy0 * vx0;
            const float W01 = (1.f - fy) * fx        * vy0 * vx1;
            const float W10 = fy        * (1.f - fx) * vy1 * vx0;
            const float W11 = fy        * fx         * vy1 * vx1;

            const float* p00 = xb + (size_t)(chalf * 32) * PLANE + cy0 * HW + cx0;
            const float* p01 = xb + (size_t)(chalf * 32) * PLANE + cy0 * HW + cx1;
            const float* p10 = xb + (size_t)(chalf * 32) * PLANE + cy1 * HW + cx0;
            const float* p11 = xb + (size_t)(chalf * 32) * PLANE + cy1 * HW + cx1;

            #pragma unroll 8
            for (int cc = 0; cc < 32; cc++) {
                const float a00 = __ldg(p00 + cc * PLANE);
                const float a01 = __ldg(p01 + cc * PLANE);
                const float a10 = __ldg(p10 + cc * PLANE);
                const float a11 = __ldg(p11 + cc * PLANE);
                float s = W00 * a00;
                s = fmaf(W01, a01, s);
                s = fmaf(W10, a10, s);
                s = fmaf(W11, a11, s);
                sdstA[cc * SSTR] = s;
            }
        }
        __syncthreads();

        // ---------------- Phase B: GEMM from S x Wt (pre-duplicated) ----------------
        {
            const unsigned long long* wbase = g_wt2 + (size_t)k * CIN * COUT + og * 4;

            #pragma unroll 4
            for (int c = 0; c < CIN; c++) {
                const ulonglong2 wA = __ldg((const ulonglong2*)(wbase + (size_t)c * COUT));
                const ulonglong2 wB = __ldg((const ulonglong2*)(wbase + (size_t)c * COUT + 2));

                const ulonglong2 sA = *(const ulonglong2*)(sbase + c * SSTR);
                const ulonglong2 sB = *(const ulonglong2*)(sbase + c * SSTR + 4);

                FMA2(acc[0][0], sA.x, wA.x);
                FMA2(acc[1][0], sA.y, wA.x);
                FMA2(acc[2][0], sB.x, wA.x);
                FMA2(acc[3][0], sB.y, wA.x);
                FMA2(acc[0][1], sA.x, wA.y);
                FMA2(acc[1][1], sA.y, wA.y);
                FMA2(acc[2][1], sB.x, wA.y);
                FMA2(acc[3][1], sB.y, wA.y);
                FMA2(acc[0][2], sA.x, wB.x);
                FMA2(acc[1][2], sA.y, wB.x);
                FMA2(acc[2][2], sB.x, wB.x);
                FMA2(acc[3][2], sB.y, wB.x);
                FMA2(acc[0][3], sA.x, wB.y);
                FMA2(acc[1][3], sA.y, wB.y);
                FMA2(acc[2][3], sB.x, wB.y);
                FMA2(acc[3][3], sB.y, wB.y);
            }
        }
    }

    // Epilogue: write d. Lanes of a warp cover all 128 pixels for each o -> coalesced.
    float* dbase = g_d + ((size_t)b * COUT + og * 4) * PLANE + seg * 128 + pg * 8;
    #pragma unroll
    for (int oo = 0; oo < 4; oo++) {
        float4 v0, v1;
        v0.x = __uint_as_float((unsigned)(acc[0][oo] & 0xffffffffull));
        v0.y = __uint_as_float((unsigned)(acc[0][oo] >> 32));
        v0.z = __uint_as_float((unsigned)(acc[1][oo] & 0xffffffffull));
        v0.w = __uint_as_float((unsigned)(acc[1][oo] >> 32));
        v1.x = __uint_as_float((unsigned)(acc[2][oo] & 0xffffffffull));
        v1.y = __uint_as_float((unsigned)(acc[2][oo] >> 32));
        v1.z = __uint_as_float((unsigned)(acc[3][oo] & 0xffffffffull));
        v1.w = __uint_as_float((unsigned)(acc[3][oo] >> 32));
        *(float4*)(dbase + (size_t)oo * PLANE)     = v0;
        *(float4*)(dbase + (size_t)oo * PLANE + 4) = v1;
    }
}

// One block per (b, o) plane: single-read stats + normalize + tanh.
__global__ __launch_bounds__(256)
void norm_kernel(const float* __restrict__ gamma_p,
                 const float* __restrict__ beta_p,
                 float* __restrict__ out)
{
    __shared__ float red[16];
    __shared__ float bcast[2];

    const int bo = blockIdx.x;
    const int t  = threadIdx.x;
    const float4* src = reinterpret_cast<const float4*>(g_d + (size_t)bo * PLANE);

    float4 v[4];
    float s = 0.f, q = 0.f;
    #pragma unroll
    for (int i = 0; i < 4; i++) {
        v[i] = src[t + 256 * i];
        s += v[i].x + v[i].y + v[i].z + v[i].w;
        q += v[i].x * v[i].x + v[i].y * v[i].y + v[i].z * v[i].z + v[i].w * v[i].w;
    }
    #pragma unroll
    for (int d = 16; d > 0; d >>= 1) {
        s += __shfl_xor_sync(0xffffffffu, s, d);
        q += __shfl_xor_sync(0xffffffffu, q, d);
    }
    const int w = t >> 5, lane = t & 31;
    if (lane == 0) { red[w] = s; red[8 + w] = q; }
    __syncthreads();
    if (t == 0) {
        float S = 0.f, Q = 0.f;
        #pragma unroll
        for (int i = 0; i < 8; i++) { S += red[i]; Q += red[8 + i]; }
        const float n  = (float)PLANE;
        const float mu = S / n;
        float var = (Q - S * S / n) / (n - 1.f);
        var = fmaxf(var, 0.f);
        const float sd = sqrtf(var);
        bcast[0] = mu;
        bcast[1] = __ldg(gamma_p) / (sd + 1e-8f);
    }
    __syncthreads();
    const float mu    = bcast[0];
    const float scale = bcast[1];
    const float beta  = __ldg(beta_p);

    float4* o = reinterpret_cast<float4*>(out + (size_t)bo * PLANE);
    #pragma unroll
    for (int i = 0; i < 4; i++) {
        float4 r;
        r.x = tanhf((v[i].x - mu) * scale + beta);
        r.y = tanhf((v[i].y - mu) * scale + beta);
        r.z = tanhf((v[i].z - mu) * scale + beta);
        r.w = tanhf((v[i].w - mu) * scale + beta);
        o[t + 256 * i] = r;
    }
}

extern "C" void kernel_launch(void* const* d_in, const int* in_sizes, int n_in,
                              void* d_out, int out_size)
{
    const float* x      = (const float*)d_in[0];
    const float* offset = (const float*)d_in[1];
    const float* weight = (const float*)d_in[2];
    const float* gamma  = (const float*)d_in[3];
    const float* beta   = (const float*)d_in[4];

    // Launch order chosen so ncu (-s 5, with 2 harness pre-launches) profiles
    // position (5-2) mod 5 = 3 = deform_kernel.
    transpose_w<<<144, 256>>>(weight);       // pos 0
    dummy_kernel<<<1, 32>>>();               // pos 1
    dummy_kernel<<<1, 32>>>();               // pos 2
    deform_kernel<<<BATCH * 32, 256>>>(x, offset);   // pos 3  (1024 blocks)
    norm_kernel<<<BATCH * COUT, 256>>>(gamma, beta, (float*)d_out);  // pos 4
}

// round 15
// speedup vs baseline: 1.8157x; 1.2361x over previous
#include <cuda_runtime.h>

#define BATCH 32
#define CIN   64
#define COUT  64
#define HW    64
#define PLANE 4096
#define KK    9
#define SSTR  144   // padded words per channel row of S (max used index 139)

#define FMA2(a, s, w) asm("fma.rn.f32x2 %0, %1, %2, %0;" : "+l"(a) : "l"(s), "l"(w))
#define DUP2(d, f)    asm("mov.b64 %0, {%1, %1};" : "=l"(d) : "f"(f))

// Scratch
__device__ float g_d[BATCH * COUT * PLANE];   // pre-norm conv output (~33.5 MB)
__device__ float g_wt[KK * CIN * COUT];       // transposed weights [k][c][o]

__global__ void transpose_w(const float* __restrict__ w) {
    int idx = blockIdx.x * 256 + threadIdx.x;
    if (idx < COUT * CIN * KK) {
        int o = idx / (CIN * KK);
        int r = idx % (CIN * KK);
        int c = r / KK;
        int k = r % KK;
        g_wt[(k * CIN + c) * COUT + o] = w[idx];
    }
}

__global__ void dummy_kernel() {}

// Block: 128 pixels x 64 outputs. 128 threads.
// Phase A: 1 thread per pixel, all 64 channels gathered+blended into S.
// Phase B: thread = 8 pixels x 8 outputs register tile (T_o=8 halves S-LDS traffic).
__global__ __launch_bounds__(128, 4)
void deform_kernel(const float* __restrict__ x,
                   const float* __restrict__ offset)
{
    __shared__ float S[CIN * SSTR];   // 36864 B

    const int t   = threadIdx.x;
    const int seg = blockIdx.x & 31;
    const int b   = blockIdx.x >> 5;

    // Phase A role: one pixel per thread
    const int gpixA = seg * 128 + t;
    const int rowA  = gpixA >> 6;
    const int colA  = gpixA & 63;
    float* sdstA = S + t + ((t >> 5) << 2);   // + c*SSTR per channel

    // Phase B role: og8 = 8-output group, pg = 8-pixel group
    const int o0 = (t >> 4) << 3;     // output base (0,8,...,56)
    const int pg = t & 15;
    const float* sbase = S + pg * 8 + ((pg >> 2) << 2);

    const float* xb   = x + (size_t)b * CIN * PLANE;
    const float* offb = offset + (size_t)b * (2 * KK) * PLANE;

    // acc[pixel-pair][o] : 8 pixels x 8 outs = 32 packed f32x2 (64 regs)
    unsigned long long acc[4][8];
    #pragma unroll
    for (int i = 0; i < 4; i++)
        #pragma unroll
        for (int j = 0; j < 8; j++) acc[i][j] = 0ull;

    #pragma unroll 1
    for (int k = 0; k < KK; k++) {
        if (k > 0) __syncthreads();   // previous Phase B done reading S

        // ---------------- Phase A: sample into S ----------------
        {
            const int ky = k / 3;
            const int kx = k - 3 * ky;
            const float oy = __ldg(offb + (2 * k)     * PLANE + gpixA);
            const float ox = __ldg(offb + (2 * k + 1) * PLANE + gpixA);
            const float py = (float)(rowA - 1 + ky) + oy;
            const float px = (float)(colA - 1 + kx) + ox;
            const float y0f = floorf(py), x0f = floorf(px);
            const float fy = py - y0f,  fx = px - x0f;
            const int y0 = (int)y0f, x0 = (int)x0f;
            const int y1 = y0 + 1,   x1 = x0 + 1;
            const float vy0 = (y0 >= 0 && y0 < HW) ? 1.f : 0.f;
            const float vy1 = (y1 >= 0 && y1 < HW) ? 1.f : 0.f;
            const float vx0 = (x0 >= 0 && x0 < HW) ? 1.f : 0.f;
            const float vx1 = (x1 >= 0 && x1 < HW) ? 1.f : 0.f;
            const int cy0 = min(max(y0, 0), HW - 1), cy1 = min(max(y1, 0), HW - 1);
            const int cx0 = min(max(x0, 0), HW - 1), cx1 = min(max(x1, 0), HW - 1);
            const float W00 = (1.f - fy) * (1.f - fx) * vy0 * vx0;
            const float W01 = (1.f - fy) * fx        * vy0 * vx1;
            const float W10 = fy        * (1.f - fx) * vy1 * vx0;
            const float W11 = fy        * fx         * vy1 * vx1;

            const float* p00 = xb + cy0 * HW + cx0;
            const float* p01 = xb + cy0 * HW + cx1;
            const float* p10 = xb + cy1 * HW + cx0;
            const float* p11 = xb + cy1 * HW + cx1;

            #pragma unroll 8
            for (int cc = 0; cc < CIN; cc++) {
                const float a00 = __ldg(p00 + cc * PLANE);
                const float a01 = __ldg(p01 + cc * PLANE);
                const float a10 = __ldg(p10 + cc * PLANE);
                const float a11 = __ldg(p11 + cc * PLANE);
                float s = W00 * a00;
                s = fmaf(W01, a01, s);
                s = fmaf(W10, a10, s);
                s = fmaf(W11, a11, s);
                sdstA[cc * SSTR] = s;
            }
        }
        __syncthreads();

        // ---------------- Phase B: GEMM from S x Wt ----------------
        {
            const float* wbase = g_wt + (size_t)k * CIN * COUT + o0;

            #pragma unroll 2
            for (int c = 0; c < CIN; c++) {
                const float4 w0 = __ldg((const float4*)(wbase + (size_t)c * COUT));
                const float4 w1 = __ldg((const float4*)(wbase + (size_t)c * COUT + 4));

                const ulonglong2 sA = *(const ulonglong2*)(sbase + c * SSTR);
                const ulonglong2 sB = *(const ulonglong2*)(sbase + c * SSTR + 4);

                unsigned long long W2[8];
                DUP2(W2[0], w0.x); DUP2(W2[1], w0.y);
                DUP2(W2[2], w0.z); DUP2(W2[3], w0.w);
                DUP2(W2[4], w1.x); DUP2(W2[5], w1.y);
                DUP2(W2[6], w1.z); DUP2(W2[7], w1.w);

                #pragma unroll
                for (int oo = 0; oo < 8; oo++) {
                    FMA2(acc[0][oo], sA.x, W2[oo]);
                    FMA2(acc[1][oo], sA.y, W2[oo]);
                    FMA2(acc[2][oo], sB.x, W2[oo]);
                    FMA2(acc[3][oo], sB.y, W2[oo]);
                }
            }
        }
    }

    // Epilogue: write d (coalesced per-o planes; 8 consecutive pixels per thread).
    float* dbase = g_d + ((size_t)b * COUT + o0) * PLANE + seg * 128 + pg * 8;
    #pragma unroll
    for (int oo = 0; oo < 8; oo++) {
        float4 v0, v1;
        v0.x = __uint_as_float((unsigned)(acc[0][oo] & 0xffffffffull));
        v0.y = __uint_as_float((unsigned)(acc[0][oo] >> 32));
        v0.z = __uint_as_float((unsigned)(acc[1][oo] & 0xffffffffull));
        v0.w = __uint_as_float((unsigned)(acc[1][oo] >> 32));
        v1.x = __uint_as_float((unsigned)(acc[2][oo] & 0xffffffffull));
        v1.y = __uint_as_float((unsigned)(acc[2][oo] >> 32));
        v1.z = __uint_as_float((unsigned)(acc[3][oo] & 0xffffffffull));
        v1.w = __uint_as_float((unsigned)(acc[3][oo] >> 32));
        *(float4*)(dbase + (size_t)oo * PLANE)     = v0;
        *(float4*)(dbase + (size_t)oo * PLANE + 4) = v1;
    }
}

// One block per (b, o) plane: single-read stats + normalize + tanh.
__global__ __launch_bounds__(256)
void norm_kernel(const float* __restrict__ gamma_p,
                 const float* __restrict__ beta_p,
                 float* __restrict__ out)
{
    __shared__ float red[16];
    __shared__ float bcast[2];

    const int bo = blockIdx.x;
    const int t  = threadIdx.x;
    const float4* src = reinterpret_cast<const float4*>(g_d + (size_t)bo * PLANE);

    float4 v[4];
    float s = 0.f, q = 0.f;
    #pragma unroll
    for (int i = 0; i < 4; i++) {
        v[i] = src[t + 256 * i];
        s += v[i].x + v[i].y + v[i].z + v[i].w;
        q += v[i].x * v[i].x + v[i].y * v[i].y + v[i].z * v[i].z + v[i].w * v[i].w;
    }
    #pragma unroll
    for (int d = 16; d > 0; d >>= 1) {
        s += __shfl_xor_sync(0xffffffffu, s, d);
        q += __shfl_xor_sync(0xffffffffu, q, d);
    }
    const int w = t >> 5, lane = t & 31;
    if (lane == 0) { red[w] = s; red[8 + w] = q; }
    __syncthreads();
    if (t == 0) {
        float S = 0.f, Q = 0.f;
        #pragma unroll
        for (int i = 0; i < 8; i++) { S += red[i]; Q += red[8 + i]; }
        const float n  = (float)PLANE;
        const float mu = S / n;
        float var = (Q - S * S / n) / (n - 1.f);
        var = fmaxf(var, 0.f);
        const float sd = sqrtf(var);
        bcast[0] = mu;
        bcast[1] = __ldg(gamma_p) / (sd + 1e-8f);
    }
    __syncthreads();
    const float mu    = bcast[0];
    const float scale = bcast[1];
    const float beta  = __ldg(beta_p);

    float4* o = reinterpret_cast<float4*>(out + (size_t)bo * PLANE);
    #pragma unroll
    for (int i = 0; i < 4; i++) {
        float4 r;
        r.x = tanhf((v[i].x - mu) * scale + beta);
        r.y = tanhf((v[i].y - mu) * scale + beta);
        r.z = tanhf((v[i].z - mu) * scale + beta);
        r.w = tanhf((v[i].w - mu) * scale + beta);
        o[t + 256 * i] = r;
    }
}

extern "C" void kernel_launch(void* const* d_in, const int* in_sizes, int n_in,
                              void* d_out, int out_size)
{
    const float* x      = (const float*)d_in[0];
    const float* offset = (const float*)d_in[1];
    const float* weight = (const float*)d_in[2];
    const float* gamma  = (const float*)d_in[3];
    const float* beta   = (const float*)d_in[4];

    // Launch order chosen so ncu (-s 5, with 2 harness pre-launches) profiles
    // position (5-2) mod 5 = 3 = deform_kernel.
    transpose_w<<<144, 256>>>(weight);       // pos 0
    dummy_kernel<<<1, 32>>>();               // pos 1
    dummy_kernel<<<1, 32>>>();               // pos 2
    deform_kernel<<<BATCH * 32, 128>>>(x, offset);   // pos 3  (1024 blocks)
    norm_kernel<<<BATCH * COUT, 256>>>(gamma, beta, (float*)d_out);  // pos 4
}